// round 3
// baseline (speedup 1.0000x reference)
#include <cuda_runtime.h>
#include <cstdint>

// Problem constants
#define Bq   64
#define Kk   4096
#define Dd   512
#define Hh   512

// Scratch (no cudaMalloc allowed): 8 MB + 128 KB device globals.
__device__ float g_qh[Bq * Hh];
__device__ float g_kh[Kk * Hh];

// ---------------------------------------------------------------------------
// f32x2 packed helpers (Blackwell sm_100a: fma.rn.f32x2 does 2 fp32 MACs/issue)
// ---------------------------------------------------------------------------
__device__ __forceinline__ unsigned long long pack2(float x, float y) {
    unsigned long long r;
    asm("mov.b64 %0, {%1, %2};" : "=l"(r) : "r"(__float_as_uint(x)), "r"(__float_as_uint(y)));
    return r;
}
__device__ __forceinline__ void fma2(unsigned long long& d,
                                     unsigned long long a, unsigned long long b) {
    asm("fma.rn.f32x2 %0, %1, %2, %0;" : "+l"(d) : "l"(a), "l"(b));
}
__device__ __forceinline__ float2 unpack2(unsigned long long v) {
    unsigned int lo, hi;
    asm("mov.b64 {%0, %1}, %2;" : "=r"(lo), "=r"(hi) : "l"(v));
    return make_float2(__uint_as_float(lo), __uint_as_float(hi));
}

// ---------------------------------------------------------------------------
// Kernel 1: qh[b][h] = query_embed[Xq[b]] . W1[:D][:,h] + b1[h]
// 64 blocks (one per b) x 512 threads (one per h). W1a stays L2-resident.
// ---------------------------------------------------------------------------
__global__ void qh_kernel(const int* __restrict__ Xq,
                          const float* __restrict__ qemb,
                          const float* __restrict__ W1,
                          const float* __restrict__ b1) {
    __shared__ float qs[Dd];
    int b = blockIdx.x;
    int h = threadIdx.x;
    int idx = Xq[b];
    qs[h] = qemb[(size_t)idx * Dd + h];
    __syncthreads();
    float acc = b1[h];
    const float* w = W1 + h;               // W1[d][h], d in [0, D)
#pragma unroll 8
    for (int d = 0; d < Dd; ++d)
        acc = fmaf(qs[d], w[(size_t)d * Hh], acc);
    g_qh[b * Hh + h] = acc;
}

// ---------------------------------------------------------------------------
// Kernel 2: kh[4096][512] = key_embed[4096][512] @ W1[D:][512][512]
// 128x128 block tile, BK=8, 256 threads, 8x8 microtile, register double
// buffer, f32x2 packed FFMA in the inner product.
// Grid: (512/128, 4096/128) = (4, 32) = 128 blocks.
// ---------------------------------------------------------------------------
#define TBM 128
#define TBN 128
#define TBK 8

__global__ __launch_bounds__(256) void kh_kernel(const float* __restrict__ A,
                                                 const float* __restrict__ Bm) {
    __shared__ float As[TBK][TBM];   // transposed A tile: As[d][m]
    __shared__ float Bs[TBK][TBN];   // Bs[d][n]

    int t  = threadIdx.x;
    int tx = t & 15;                 // n direction (16)
    int ty = t >> 4;                 // m direction (16)
    int bn0 = blockIdx.x * TBN;
    int bm0 = blockIdx.y * TBM;

    // global-load mapping
    int arow = t >> 1;               // 0..127
    int acol = (t & 1) * 4;          // 0 or 4
    int brow = t >> 6;               // 0..3  (we load 2 rows per thread)
    int bcol = (t & 63) * 4;         // covers 256 floats... adjust below

    // Simpler exact mapping: A tile 128x8 = 1024 floats -> 1 float4/thread
    //                        B tile 8x128 = 1024 floats -> 1 float4/thread
    brow = t >> 5;                   // 0..7
    bcol = (t & 31) * 4;             // 0..124

    const float* Aptr = A  + (size_t)(bm0 + arow) * Dd + acol;
    const float* Bptr = Bm + (size_t)brow * Hh + bn0 + bcol;

    unsigned long long acc[8][4];
#pragma unroll
    for (int i = 0; i < 8; ++i)
#pragma unroll
        for (int p = 0; p < 4; ++p) acc[i][p] = 0ULL;

    float4 a4 = *(const float4*)Aptr;
    float4 b4 = *(const float4*)Bptr;

    for (int kc = 0; kc < Dd; kc += TBK) {
        // commit staged registers to smem
        As[acol + 0][arow] = a4.x;
        As[acol + 1][arow] = a4.y;
        As[acol + 2][arow] = a4.z;
        As[acol + 3][arow] = a4.w;
        *(float4*)&Bs[brow][bcol] = b4;
        __syncthreads();

        // prefetch next k-chunk into registers (hides L2 latency behind math)
        if (kc + TBK < Dd) {
            a4 = *(const float4*)(Aptr + kc + TBK);
            b4 = *(const float4*)(Bptr + (size_t)(kc + TBK) * Hh);
        }

#pragma unroll
        for (int d = 0; d < TBK; ++d) {
            float a[8];
            *(float4*)&a[0] = *(const float4*)&As[d][4 * ty];
            *(float4*)&a[4] = *(const float4*)&As[d][64 + 4 * ty];
            unsigned long long bb[4];
            bb[0] = *(const unsigned long long*)&Bs[d][4 * tx];
            bb[1] = *(const unsigned long long*)&Bs[d][4 * tx + 2];
            bb[2] = *(const unsigned long long*)&Bs[d][64 + 4 * tx];
            bb[3] = *(const unsigned long long*)&Bs[d][64 + 4 * tx + 2];
#pragma unroll
            for (int i = 0; i < 8; ++i) {
                unsigned long long aa = pack2(a[i], a[i]);
                fma2(acc[i][0], aa, bb[0]);
                fma2(acc[i][1], aa, bb[1]);
                fma2(acc[i][2], aa, bb[2]);
                fma2(acc[i][3], aa, bb[3]);
            }
        }
        __syncthreads();
    }

#pragma unroll
    for (int i = 0; i < 8; ++i) {
        int row = bm0 + ((i < 4) ? (4 * ty + i) : (64 + 4 * ty + (i - 4)));
        float2 p0 = unpack2(acc[i][0]);
        float2 p1 = unpack2(acc[i][1]);
        float2 p2 = unpack2(acc[i][2]);
        float2 p3 = unpack2(acc[i][3]);
        *(float4*)&g_kh[(size_t)row * Hh + bn0 + 4 * tx]      = make_float4(p0.x, p0.y, p1.x, p1.y);
        *(float4*)&g_kh[(size_t)row * Hh + bn0 + 64 + 4 * tx] = make_float4(p2.x, p2.y, p3.x, p3.y);
    }
}

// ---------------------------------------------------------------------------
// Kernel 3: logits[b][k] = sum_h relu(qh[b][h] + kh[k][h]) * w2[h] + b2
// Block tile: all 64 b x 32 k, h streamed in chunks of 32 via transposed
// smem tiles (padded pitches 65 / 33 -> conflict-free transpose + compute).
// 256 threads, 4(b) x 2(k) per thread. Grid: 4096/32 = 128 blocks.
// ---------------------------------------------------------------------------
#define CK 32
#define CH 32

__global__ __launch_bounds__(256) void logits_kernel(const float* __restrict__ W2,
                                                     const float* __restrict__ b2,
                                                     float* __restrict__ out) {
    __shared__ float qs[CH][65];   // [h][b], pad 65 -> conflict-free
    __shared__ float ks[CH][33];   // [h][k], pad 33
    __shared__ float w2s[CH];

    int t  = threadIdx.x;
    int tk = t & 15;
    int tb = t >> 4;
    int k0 = blockIdx.x * CK;

    float acc[4][2] = {};

    for (int h0 = 0; h0 < Hh; h0 += CH) {
        // qh tile: 64 b x 32 h, transposed store
#pragma unroll
        for (int i = 0; i < 8; ++i) {
            int lin = t + i * 256;              // 0..2047
            int b = lin >> 5, hh = lin & 31;
            qs[hh][b] = g_qh[b * Hh + h0 + hh];
        }
        // kh tile: 32 k x 32 h, transposed store
#pragma unroll
        for (int i = 0; i < 4; ++i) {
            int lin = t + i * 256;              // 0..1023
            int k = lin >> 5, hh = lin & 31;
            ks[hh][k] = g_kh[(size_t)(k0 + k) * Hh + h0 + hh];
        }
        if (t < CH) w2s[t] = W2[h0 + t];
        __syncthreads();

#pragma unroll 4
        for (int hh = 0; hh < CH; ++hh) {
            float w   = w2s[hh];
            float kv0 = ks[hh][tk];
            float kv1 = ks[hh][tk + 16];
#pragma unroll
            for (int i = 0; i < 4; ++i) {
                float qv = qs[hh][tb + 16 * i];
                acc[i][0] = fmaf(fmaxf(qv + kv0, 0.f), w, acc[i][0]);
                acc[i][1] = fmaf(fmaxf(qv + kv1, 0.f), w, acc[i][1]);
            }
        }
        __syncthreads();
    }

    float bias = b2[0];
#pragma unroll
    for (int i = 0; i < 4; ++i) {
        int b = tb + 16 * i;
        out[(size_t)b * Kk + k0 + tk]      = acc[i][0] + bias;
        out[(size_t)b * Kk + k0 + tk + 16] = acc[i][1] + bias;
    }
}

// ---------------------------------------------------------------------------
// Inputs (metadata order): X_query(int32, 64), query_embed(f32, 8192x512),
// key_embed(f32, 4096x512), W1(f32, 1024x512), b1(f32, 512),
// W2(f32, 512x1), b2(f32, 1). Output: f32, 64x4096.
// ---------------------------------------------------------------------------
extern "C" void kernel_launch(void* const* d_in, const int* in_sizes, int n_in,
                              void* d_out, int out_size) {
    const int*   Xq   = (const int*)d_in[0];
    const float* qemb = (const float*)d_in[1];
    const float* kemb = (const float*)d_in[2];
    const float* W1   = (const float*)d_in[3];
    const float* b1   = (const float*)d_in[4];
    const float* W2   = (const float*)d_in[5];
    const float* b2   = (const float*)d_in[6];
    float* out = (float*)d_out;

    // qh: tiny GEMM with embedding gather
    qh_kernel<<<Bq, Dd>>>(Xq, qemb, W1, b1);

    // kh: 4096x512x512 GEMM, B-matrix = W1 rows [D, 2D)
    dim3 g2(Hh / TBN, Kk / TBM);     // (4, 32)
    kh_kernel<<<g2, 256>>>(kemb, W1 + (size_t)Dd * Hh);

    // fused relu-broadcast-reduce
    logits_kernel<<<Kk / CK, 256>>>(W2, b2, out);
}

// round 4
// speedup vs baseline: 1.0520x; 1.0520x over previous
#include <cuda_runtime.h>
#include <cstdint>

// Problem constants
#define Bq   64
#define Kk   4096
#define Dd   512
#define Hh   512

// Scratch (no cudaMalloc allowed)
__device__ float g_qh[Bq * Hh];
__device__ float g_kh[Kk * Hh];

// ---------------------------------------------------------------------------
// f32x2 packed helpers
// ---------------------------------------------------------------------------
__device__ __forceinline__ unsigned long long pack2(float x, float y) {
    unsigned long long r;
    asm("mov.b64 %0, {%1, %2};" : "=l"(r) : "r"(__float_as_uint(x)), "r"(__float_as_uint(y)));
    return r;
}
__device__ __forceinline__ void fma2(unsigned long long& d,
                                     unsigned long long a, unsigned long long b) {
    asm("fma.rn.f32x2 %0, %1, %2, %0;" : "+l"(d) : "l"(a), "l"(b));
}
__device__ __forceinline__ unsigned long long add2(unsigned long long a,
                                                   unsigned long long b) {
    unsigned long long r;
    asm("add.rn.f32x2 %0, %1, %2;" : "=l"(r) : "l"(a), "l"(b));
    return r;
}
__device__ __forceinline__ float2 unpack2(unsigned long long v) {
    unsigned int lo, hi;
    asm("mov.b64 {%0, %1}, %2;" : "=r"(lo), "=r"(hi) : "l"(v));
    return make_float2(__uint_as_float(lo), __uint_as_float(hi));
}

// ---------------------------------------------------------------------------
// Fused kernel: blocks [0,128) compute kh' = key_embed @ W1[D:] + b1
//               blocks [128,160) compute qh = gather(query_embed) @ W1[:D]
// qh blocks (short) run concurrently on the SMs kh (128 blocks) leaves free.
// ---------------------------------------------------------------------------
#define TBM 128
#define TBN 128
#define TBK 8

__global__ __launch_bounds__(256) void fused_qh_kh(const int* __restrict__ Xq,
                                                   const float* __restrict__ qemb,
                                                   const float* __restrict__ kemb,
                                                   const float* __restrict__ W1,
                                                   const float* __restrict__ b1) {
    __shared__ union {
        struct { float As[TBK][TBM]; float Bs[TBK][TBN]; } g;   // 8 KB
        float qs[Dd][4];                                         // 8 KB
    } sm;

    int t = threadIdx.x;

    if (blockIdx.x < 128) {
        // ------------------- kh role: 128x128 tile GEMM + b1 -------------------
        const float* A  = kemb;
        const float* Bm = W1 + (size_t)Dd * Hh;   // W1[D:, :]

        int tx = t & 15;                 // n direction (16)
        int ty = t >> 4;                 // m direction (16)
        int bn0 = (blockIdx.x & 3) * TBN;
        int bm0 = (blockIdx.x >> 2) * TBM;

        int arow = t >> 1;               // 0..127
        int acol = (t & 1) * 4;          // 0 or 4
        int brow = t >> 5;               // 0..7
        int bcol = (t & 31) * 4;         // 0..124

        const float* Aptr = A  + (size_t)(bm0 + arow) * Dd + acol;
        const float* Bptr = Bm + (size_t)brow * Hh + bn0 + bcol;

        unsigned long long acc[8][4];
#pragma unroll
        for (int i = 0; i < 8; ++i)
#pragma unroll
            for (int p = 0; p < 4; ++p) acc[i][p] = 0ULL;

        float4 a4 = *(const float4*)Aptr;
        float4 b4 = *(const float4*)Bptr;

        for (int kc = 0; kc < Dd; kc += TBK) {
            sm.g.As[acol + 0][arow] = a4.x;
            sm.g.As[acol + 1][arow] = a4.y;
            sm.g.As[acol + 2][arow] = a4.z;
            sm.g.As[acol + 3][arow] = a4.w;
            *(float4*)&sm.g.Bs[brow][bcol] = b4;
            __syncthreads();

            if (kc + TBK < Dd) {
                a4 = *(const float4*)(Aptr + kc + TBK);
                b4 = *(const float4*)(Bptr + (size_t)(kc + TBK) * Hh);
            }

#pragma unroll
            for (int d = 0; d < TBK; ++d) {
                float a[8];
                *(float4*)&a[0] = *(const float4*)&sm.g.As[d][4 * ty];
                *(float4*)&a[4] = *(const float4*)&sm.g.As[d][64 + 4 * ty];
                unsigned long long bb[4];
                bb[0] = *(const unsigned long long*)&sm.g.Bs[d][4 * tx];
                bb[1] = *(const unsigned long long*)&sm.g.Bs[d][4 * tx + 2];
                bb[2] = *(const unsigned long long*)&sm.g.Bs[d][64 + 4 * tx];
                bb[3] = *(const unsigned long long*)&sm.g.Bs[d][64 + 4 * tx + 2];
#pragma unroll
                for (int i = 0; i < 8; ++i) {
                    unsigned long long aa = pack2(a[i], a[i]);
                    fma2(acc[i][0], aa, bb[0]);
                    fma2(acc[i][1], aa, bb[1]);
                    fma2(acc[i][2], aa, bb[2]);
                    fma2(acc[i][3], aa, bb[3]);
                }
            }
            __syncthreads();
        }

        // b1 folded in here (kh' = k@W1b + b1) so qh stays a pure GEMM
        float4 bv0 = *(const float4*)&b1[bn0 + 4 * tx];
        float4 bv1 = *(const float4*)&b1[bn0 + 64 + 4 * tx];

#pragma unroll
        for (int i = 0; i < 8; ++i) {
            int row = bm0 + ((i < 4) ? (4 * ty + i) : (64 + 4 * ty + (i - 4)));
            float2 p0 = unpack2(acc[i][0]);
            float2 p1 = unpack2(acc[i][1]);
            float2 p2 = unpack2(acc[i][2]);
            float2 p3 = unpack2(acc[i][3]);
            *(float4*)&g_kh[(size_t)row * Hh + bn0 + 4 * tx] =
                make_float4(p0.x + bv0.x, p0.y + bv0.y, p1.x + bv0.z, p1.y + bv0.w);
            *(float4*)&g_kh[(size_t)row * Hh + bn0 + 64 + 4 * tx] =
                make_float4(p2.x + bv1.x, p2.y + bv1.y, p3.x + bv1.z, p3.y + bv1.w);
        }
    } else {
        // ------------------- qh role: 4 b x 256 h per block -------------------
        int r  = blockIdx.x - 128;       // 0..31
        int hc = r & 1;                  // h chunk (2 x 256)
        int bg = r >> 1;                 // b group (16 x 4)
        int h  = hc * 256 + t;
        int b0 = bg * 4;

        // load 4 q rows transposed into smem: qs[d][bi]
        int bi   = t >> 6;               // 0..3
        int lane = t & 63;               // 0..63
        const float* qrow = qemb + (size_t)Xq[b0 + bi] * Dd;
#pragma unroll
        for (int j = 0; j < 8; ++j) {
            int d = lane + 64 * j;
            sm.qs[d][bi] = qrow[d];
        }
        __syncthreads();

        const float* w = W1 + h;         // W1[d][h], d in [0, D)
        unsigned long long acc01 = 0ULL, acc23 = 0ULL;
#pragma unroll 8
        for (int d = 0; d < Dd; ++d) {
            float wv = w[(size_t)d * Hh];
            float4 q4 = *(const float4*)&sm.qs[d][0];   // broadcast
            unsigned long long ws = pack2(wv, wv);
            fma2(acc01, pack2(q4.x, q4.y), ws);
            fma2(acc23, pack2(q4.z, q4.w), ws);
        }

        float2 p01 = unpack2(acc01);
        float2 p23 = unpack2(acc23);
        g_qh[(b0 + 0) * Hh + h] = p01.x;
        g_qh[(b0 + 1) * Hh + h] = p01.y;
        g_qh[(b0 + 2) * Hh + h] = p23.x;
        g_qh[(b0 + 3) * Hh + h] = p23.y;
    }
}

// ---------------------------------------------------------------------------
// Logits: logits[b][k] = sum_h relu(qh[b][h] + kh'[k][h]) * w2[h] + b2
// Packed exact relu: t = s + |s| = 2*relu(s), with w/2 pre-folded.
// Block: 32 k x 64 b, h streamed in chunks of 32. 256 threads,
// thread tile = 2 b x 2 k-pairs (4 k). Grid: 4096/32 = 128 blocks.
// ---------------------------------------------------------------------------
#define CK 32
#define CH 32

__global__ __launch_bounds__(256) void logits_kernel(const float* __restrict__ W2,
                                                     const float* __restrict__ b2,
                                                     float* __restrict__ out) {
    __shared__ float qs[CH][65];                 // [h][b]
    __shared__ float ks[CH][34];                 // [h][k], even pitch for LDS.64
    __shared__ unsigned long long w2p[CH];       // packed (w/2, w/2)

    const unsigned long long ABSM = 0x7FFFFFFF7FFFFFFFULL;

    int t   = threadIdx.x;
    int tkp = t & 7;                 // k-pair group (8): pairs at 2*tkp, 2*tkp+16
    int tb  = t >> 3;                // b base (32): b = tb, tb+32
    int k0  = blockIdx.x * CK;

    unsigned long long acc[2][2] = {{0ULL, 0ULL}, {0ULL, 0ULL}};

    for (int h0 = 0; h0 < Hh; h0 += CH) {
        // qh tile: 64 b x 32 h, transposed
#pragma unroll
        for (int i = 0; i < 8; ++i) {
            int lin = t + i * 256;               // 0..2047
            int b = lin >> 5, hh = lin & 31;
            qs[hh][b] = g_qh[b * Hh + h0 + hh];
        }
        // kh tile: 32 k x 32 h, transposed
#pragma unroll
        for (int i = 0; i < 4; ++i) {
            int lin = t + i * 256;               // 0..1023
            int k = lin >> 5, hh = lin & 31;
            ks[hh][k] = g_kh[(size_t)(k0 + k) * Hh + h0 + hh];
        }
        if (t < CH) {
            float wv = W2[h0 + t] * 0.5f;
            w2p[t] = pack2(wv, wv);
        }
        __syncthreads();

#pragma unroll 4
        for (int hh = 0; hh < CH; ++hh) {
            unsigned long long w2 = w2p[hh];
            unsigned long long kk0 = *(const unsigned long long*)&ks[hh][2 * tkp];
            unsigned long long kk1 = *(const unsigned long long*)&ks[hh][2 * tkp + 16];
#pragma unroll
            for (int bi = 0; bi < 2; ++bi) {
                float qv = qs[hh][tb + 32 * bi];
                unsigned long long qq = pack2(qv, qv);
                unsigned long long s0 = add2(qq, kk0);
                unsigned long long s1 = add2(qq, kk1);
                s0 = add2(s0, s0 & ABSM);        // = 2*relu, exact
                s1 = add2(s1, s1 & ABSM);
                fma2(acc[bi][0], s0, w2);
                fma2(acc[bi][1], s1, w2);
            }
        }
        __syncthreads();
    }

    float bias = b2[0];
#pragma unroll
    for (int bi = 0; bi < 2; ++bi) {
        int b = tb + 32 * bi;
        float2 r0 = unpack2(acc[bi][0]);
        float2 r1 = unpack2(acc[bi][1]);
        *(float2*)&out[(size_t)b * Kk + k0 + 2 * tkp] =
            make_float2(r0.x + bias, r0.y + bias);
        *(float2*)&out[(size_t)b * Kk + k0 + 2 * tkp + 16] =
            make_float2(r1.x + bias, r1.y + bias);
    }
}

// ---------------------------------------------------------------------------
// Inputs (metadata order): X_query(int32, 64), query_embed(f32, 8192x512),
// key_embed(f32, 4096x512), W1(f32, 1024x512), b1(f32, 512),
// W2(f32, 512x1), b2(f32, 1). Output: f32, 64x4096.
// ---------------------------------------------------------------------------
extern "C" void kernel_launch(void* const* d_in, const int* in_sizes, int n_in,
                              void* d_out, int out_size) {
    const int*   Xq   = (const int*)d_in[0];
    const float* qemb = (const float*)d_in[1];
    const float* kemb = (const float*)d_in[2];
    const float* W1   = (const float*)d_in[3];
    const float* b1   = (const float*)d_in[4];
    const float* W2   = (const float*)d_in[5];
    const float* b2   = (const float*)d_in[6];
    float* out = (float*)d_out;

    // fused qh + kh (qh blocks hide under kh)
    fused_qh_kh<<<160, 256>>>(Xq, qemb, kemb, W1, b1);

    // fused relu-broadcast-reduce
    logits_kernel<<<Kk / CK, 256>>>(W2, b2, out);
}